// round 16
// baseline (speedup 1.0000x reference)
#include <cuda_runtime.h>
#include <cuda_bf16.h>
#include <cstdint>

// Q=512, M=512, B=8, D=1024, H=16, DH=64, DI=4096, K=1024
#define QLEN 512
#define BSZ 8
#define DMODEL 1024
#define DINNER 4096
#define KLEN 1024

// ---------------- fp32 scratch ----------------------------------------------
__device__ float g_qkv[(size_t)KLEN * BSZ * 3 * DMODEL];     // (k*8+b, 3072)
__device__ float g_rk[(size_t)KLEN * DMODEL];
__device__ float g_bbd[(size_t)16 * KLEN];
__device__ float g_attnout[(size_t)QLEN * BSZ * DMODEL];
__device__ float g_out1[(size_t)QLEN * BSZ * DMODEL];
__device__ float g_ffo[(size_t)QLEN * BSZ * DMODEL];

// ---------------- bf16 split scratch ([hi|lo], 2K-wide rows) -----------------
__device__ __nv_bfloat16 g_aqkv[(size_t)8192 * 2048];
__device__ __nv_bfloat16 g_bqkv[(size_t)3072 * 2048];
__device__ __nv_bfloat16 g_ar[(size_t)1024 * 2048];
__device__ __nv_bfloat16 g_br[(size_t)1024 * 2048];
__device__ __nv_bfloat16 g_awo[(size_t)4096 * 2048];
__device__ __nv_bfloat16 g_bwo[(size_t)1024 * 2048];
__device__ __nv_bfloat16 g_aff1[(size_t)4096 * 2048];
__device__ __nv_bfloat16 g_bff1[(size_t)4096 * 2048];
__device__ __nv_bfloat16 g_aff2[(size_t)4096 * 8192];
__device__ __nv_bfloat16 g_bff2[(size_t)1024 * 8192];

// ---------------- PTX helpers -----------------------------------------------
__device__ __forceinline__ uint32_t smem_u32(const void* p) {
    uint32_t a;
    asm("{ .reg .u64 t; cvta.to.shared.u64 t, %1; cvt.u32.u64 %0, t; }"
        : "=r"(a) : "l"(p));
    return a;
}
#define CP16(dst, src) \
    asm volatile("cp.async.cg.shared.global [%0], [%1], 16;" :: "r"(dst), "l"(src))
#define CP_COMMIT() asm volatile("cp.async.commit_group;" ::: "memory")
#define CP_WAIT2() asm volatile("cp.async.wait_group 2;" ::: "memory")

__device__ __forceinline__ void ldsm4(uint32_t* r, uint32_t addr) {
    asm volatile(
        "ldmatrix.sync.aligned.m8n8.x4.shared.b16 {%0,%1,%2,%3}, [%4];"
        : "=r"(r[0]), "=r"(r[1]), "=r"(r[2]), "=r"(r[3]) : "r"(addr));
}
__device__ __forceinline__ void ldsm4t(uint32_t* r, uint32_t addr) {
    asm volatile(
        "ldmatrix.sync.aligned.m8n8.x4.trans.shared.b16 {%0,%1,%2,%3}, [%4];"
        : "=r"(r[0]), "=r"(r[1]), "=r"(r[2]), "=r"(r[3]) : "r"(addr));
}
__device__ __forceinline__ void mma16816(float* d, const uint32_t* a,
                                         uint32_t b0, uint32_t b1) {
    asm volatile(
        "mma.sync.aligned.m16n8k16.row.col.f32.bf16.bf16.f32 "
        "{%0,%1,%2,%3}, {%4,%5,%6,%7}, {%8,%9}, {%0,%1,%2,%3};"
        : "+f"(d[0]), "+f"(d[1]), "+f"(d[2]), "+f"(d[3])
        : "r"(a[0]), "r"(a[1]), "r"(a[2]), "r"(a[3]), "r"(b0), "r"(b1));
}

__device__ __forceinline__ __nv_bfloat162 split_hi2(float x, float y,
                                                    __nv_bfloat162* lo) {
    __nv_bfloat162 h = __floats2bfloat162_rn(x, y);
    *lo = __floats2bfloat162_rn(x - __bfloat162float(h.x),
                                y - __bfloat162float(h.y));
    return h;
}
__device__ __forceinline__ void split4(float4 v, uint2* hi, uint2* lo) {
    __nv_bfloat162 l01, l23;
    __nv_bfloat162 h01 = split_hi2(v.x, v.y, &l01);
    __nv_bfloat162 h23 = split_hi2(v.z, v.w, &l23);
    hi->x = *(uint32_t*)&h01; hi->y = *(uint32_t*)&h23;
    lo->x = *(uint32_t*)&l01; lo->y = *(uint32_t*)&l23;
}

// ---------------- fp32 -> bf16 [hi|lo] split (rows 2K wide) ------------------
__global__ __launch_bounds__(256) void split3(const float* __restrict__ src,
                                              __nv_bfloat16* __restrict__ dst,
                                              int lk, long long n)
{
    long long K = 1LL << lk;
    long long i0 = ((long long)blockIdx.x * 256 + threadIdx.x) * 4;
    long long step = (long long)gridDim.x * 256 * 4;
    for (long long e = i0; e < n; e += step) {
        long long r = e >> lk;
        long long k = e & (K - 1);
        float4 v = *(const float4*)(src + e);
        __nv_bfloat162 l01, l23;
        __nv_bfloat162 h01 = split_hi2(v.x, v.y, &l01);
        __nv_bfloat162 h23 = split_hi2(v.z, v.w, &l23);
        __nv_bfloat16* base = dst + r * (K * 2) + k;
        *(__nv_bfloat162*)(base) = h01;
        *(__nv_bfloat162*)(base + 2) = h23;
        *(__nv_bfloat162*)(base + K) = l01;
        *(__nv_bfloat162*)(base + K + 2) = l23;
    }
}

// ---------------- bf16 tensor-core GEMM (2K layout, R7 loop order) -----------
// C[M,N] fp32 (optional) and/or Csplit ([hi|lo], rows 2N wide)
//   = split-3 product of A[M,2K], B[N,2K] ([hi|lo] K-major) + bias, opt relu.
// Pass 0: Ahi*Bhi, pass 1: Alo*Bhi, pass 2: Ahi*Blo.
#define STAGE_BYTES 32768
#define GEMM_DYN_SMEM (3 * STAGE_BYTES)
#define SWZ(x) ((x) ^ (((x) >> 3) & 0x70))

__global__ __launch_bounds__(256, 2) void gemm_bf16_mma(
    const __nv_bfloat16* __restrict__ A, const __nv_bfloat16* __restrict__ B,
    const float* __restrict__ bias, float* __restrict__ C,
    __nv_bfloat16* __restrict__ Csplit,
    int M, int N, int K, int relu)
{
    extern __shared__ char dynsm[];
    const int tid = threadIdx.x;
    const int wid = tid >> 5, lane = tid & 31;
    const int wm = wid & 3, wn = wid >> 2;
    const int bm = blockIdx.y * 128, bn = blockIdx.x * 128;
    const int nk = K >> 6;
    const int nchunks = 3 * nk;
    const uint32_t smbase = smem_u32(dynsm);
    const size_t rowBytes = (size_t)K * 4;  // 2K bf16

    uint32_t dstOff[4];
    const char* baseA[4];
    const char* baseB[4];
    {
        int r0 = tid >> 3;
        int c16 = (tid & 7) << 4;
#pragma unroll
        for (int i = 0; i < 4; i++) {
            int row = r0 + i * 32;
            dstOff[i] = SWZ((uint32_t)(row * 128 + c16));
            baseA[i] = (const char*)A + (size_t)(bm + row) * rowBytes + c16;
            baseB[i] = (const char*)B + (size_t)(bn + row) * rowBytes + c16;
        }
    }

    float acc[2][8][4];
#pragma unroll
    for (int t = 0; t < 2; t++)
#pragma unroll
        for (int j = 0; j < 8; j++)
#pragma unroll
            for (int q = 0; q < 4; q++) acc[t][j][q] = 0.f;

    auto issue_copies = [&](int chunk) {
        int kk, aB, bB;
        if (chunk >= 2 * nk)      { kk = chunk - 2 * nk; aB = 0;     bB = 2 * K; }
        else if (chunk >= nk)     { kk = chunk - nk;     aB = 2 * K; bB = 0;     }
        else                      { kk = chunk;          aB = 0;     bB = 0;     }
        size_t aOff = (size_t)aB + (size_t)kk * 128;
        size_t bOff = (size_t)bB + (size_t)kk * 128;
        uint32_t sbuf = smbase + (chunk % 3) * STAGE_BYTES;
#pragma unroll
        for (int i = 0; i < 4; i++) {
            CP16(sbuf + dstOff[i], baseA[i] + aOff);
            CP16(sbuf + 16384 + dstOff[i], baseB[i] + bOff);
        }
    };

    issue_copies(0); CP_COMMIT();
    issue_copies(1); CP_COMMIT();

    uint32_t preA[2], preB[4];
#pragma unroll
    for (int t = 0; t < 2; t++) {
        int row = wm * 32 + t * 16 + (lane & 15);
        preA[t] = (uint32_t)(row * 128 + ((row & 7) << 4));
    }
#pragma unroll
    for (int p = 0; p < 4; p++) {
        int row = wn * 64 + p * 16 + (lane & 15);
        preB[p] = (uint32_t)(row * 128 + ((row & 7) << 4));
    }
    const uint32_t kbase = (uint32_t)((lane >> 4) << 4);

    for (int c = 0; c < nchunks; c++) {
        if (c + 2 < nchunks) issue_copies(c + 2);
        CP_COMMIT();
        CP_WAIT2();
        __syncthreads();

        const uint32_t sA = smbase + (c % 3) * STAGE_BYTES;
        const uint32_t sB = sA + 16384;

#pragma unroll
        for (int kk = 0; kk < 4; kk++) {
            const uint32_t kb = (uint32_t)(kk * 32) + kbase;
            uint32_t a[2][4], b[4][4];
#pragma unroll
            for (int t = 0; t < 2; t++) ldsm4(a[t], sA + (preA[t] ^ kb));
#pragma unroll
            for (int p = 0; p < 4; p++) ldsm4(b[p], sB + (preB[p] ^ kb));
#pragma unroll
            for (int t = 0; t < 2; t++)
#pragma unroll
                for (int j = 0; j < 8; j++)
                    mma16816(acc[t][j], a[t], b[j >> 1][j & 1],
                             b[j >> 1][2 + (j & 1)]);
        }
        __syncthreads();
    }

#pragma unroll
    for (int t = 0; t < 2; t++) {
        int row0 = bm + wm * 32 + t * 16 + (lane >> 2);
#pragma unroll
        for (int j = 0; j < 8; j++) {
            int col = bn + wn * 64 + j * 8 + (lane & 3) * 2;
            float bx = 0.f, by = 0.f;
            if (bias) { bx = bias[col]; by = bias[col + 1]; }
            float2 v0 = make_float2(acc[t][j][0] + bx, acc[t][j][1] + by);
            float2 v1 = make_float2(acc[t][j][2] + bx, acc[t][j][3] + by);
            if (relu) {
                v0.x = fmaxf(v0.x, 0.f); v0.y = fmaxf(v0.y, 0.f);
                v1.x = fmaxf(v1.x, 0.f); v1.y = fmaxf(v1.y, 0.f);
            }
            if (C) {
                *(float2*)(C + (size_t)row0 * N + col) = v0;
                *(float2*)(C + (size_t)(row0 + 8) * N + col) = v1;
            }
            if (Csplit) {
                __nv_bfloat162 lo0, lo1;
                __nv_bfloat162 h0 = split_hi2(v0.x, v0.y, &lo0);
                __nv_bfloat162 h1 = split_hi2(v1.x, v1.y, &lo1);
                __nv_bfloat16* p0 = Csplit + (size_t)row0 * (2 * N) + col;
                __nv_bfloat16* p1 = Csplit + (size_t)(row0 + 8) * (2 * N) + col;
                *(__nv_bfloat162*)(p0) = h0;
                *(__nv_bfloat162*)(p0 + N) = lo0;
                *(__nv_bfloat162*)(p1) = h1;
                *(__nv_bfloat162*)(p1 + N) = lo1;
            }
        }
    }
}

// ---------------- bias dot: bbd[h,l] = (rrb-rwb)[h,:] . rk[l,h,:] ------------
__global__ void bias_bd_kernel(const float* __restrict__ rk,
                               const float* __restrict__ rrb,
                               const float* __restrict__ rwb,
                               float* __restrict__ out)
{
    int warp = (blockIdx.x * blockDim.x + threadIdx.x) >> 5;
    int lane = threadIdx.x & 31;
    int l = warp & 1023;
    int h = warp >> 10;
    const float* kp = rk + (size_t)l * 1024 + h * 64;
    float w0 = rrb[h * 64 + lane] - rwb[h * 64 + lane];
    float w1 = rrb[h * 64 + lane + 32] - rwb[h * 64 + lane + 32];
    float v = kp[lane] * w0 + kp[lane + 32] * w1;
#pragma unroll
    for (int off = 16; off >= 1; off >>= 1)
        v += __shfl_xor_sync(0xffffffffu, v, off);
    if (lane == 0) out[warp] = v;
}

// ---------------- MMA rel-shift flash attention (q+rwb fused) ----------------
#define AQ   0
#define AKS  17408
#define AS   17408
#define AV   69632
#define AP   88064
#define ABBD 105728
#define AMS  106240
#define ALS  106496
#define ACR  106752
#define ATT_SMEM 107008

__global__ __launch_bounds__(256, 2) void attn_mma3(
    const float* __restrict__ qkv, const float* __restrict__ rkG,
    const float* __restrict__ rwb, const float* __restrict__ bbd_g,
    __nv_bfloat16* __restrict__ outSplit)
{
    extern __shared__ char sm[];
    const uint32_t sb = smem_u32(sm);
    const int tid = threadIdx.x, lane = tid & 31, wid = tid >> 5;
    const int wm = wid & 3, wn = wid >> 2;
    const int i0 = blockIdx.x * 64, h = blockIdx.y, b = blockIdx.z;

    float* msm = (float*)(sm + AMS);
    float* lsm = (float*)(sm + ALS);
    float* crs = (float*)(sm + ACR);
    float* bbds = (float*)(sm + ABBD);

    if (tid < 64) { msm[tid] = -1e30f; lsm[tid] = 0.f; }

    // q tile: fp32 load + rwb bias, split -> [hi 128B | lo 128B], stride 272
#pragma unroll
    for (int i = 0; i < 4; i++) {
        int idx = tid + i * 256;
        int row = idx >> 4, d4 = (idx & 15) * 4;
        float4 v = *(const float4*)(qkv +
            ((size_t)(512 + i0 + row) * 8 + b) * 3072 + h * 64 + d4);
        float4 wv = *(const float4*)(rwb + h * 64 + d4);
        v.x += wv.x; v.y += wv.y; v.z += wv.z; v.w += wv.w;
        uint2 hi, lo;
        split4(v, &hi, &lo);
        char* base = sm + AQ + row * 272 + d4 * 2;
        *(uint2*)(base) = hi;
        *(uint2*)(base + 128) = lo;
    }

    float oacc[4][4];
#pragma unroll
    for (int j = 0; j < 4; j++)
#pragma unroll
        for (int q = 0; q < 4; q++) oacc[j][q] = 0.f;

    const int aoff[12] = {0,32,64,96, 128,160,192,224, 0,32,64,96};
    const int boff[12] = {0,32,64,96, 0,32,64,96, 128,160,192,224};
    const int pvjr[12] = {0,16,32,48, 0,16,32,48, 64,80,96,112};

    const int n_jt = min(16, (int)blockIdx.x + 9);
    const uint32_t koff = (uint32_t)((lane >> 4) << 4);

    for (int jt = 0; jt < n_jt; jt++) {
        const int j0 = jt * 64;
        const int l0 = j0 + 448 - i0;

        __syncthreads();

#pragma unroll
        for (int i = 0; i < 4; i++) {
            int idx = tid + i * 256;
            int jj = idx >> 4, d4 = (idx & 15) * 4;
            float4 v = *(const float4*)(qkv +
                ((size_t)(j0 + jj) * 8 + b) * 3072 + 1024 + h * 64 + d4);
            uint2 hi, lo;
            split4(v, &hi, &lo);
            char* base = sm + AKS + jj * 272 + d4 * 2;
            *(uint2*)(base) = hi;
            *(uint2*)(base + 128) = lo;
        }
#pragma unroll
        for (int i = 0; i < 8; i++) {
            int idx = tid + i * 256;
            int t = idx >> 4, d4 = (idx & 15) * 4;
            int l = l0 + t;
            float4 v = make_float4(0.f, 0.f, 0.f, 0.f);
            if (l < 1024)
                v = *(const float4*)(rkG + (size_t)l * 1024 + h * 64 + d4);
            uint2 hi, lo;
            split4(v, &hi, &lo);
            char* base = sm + AKS + (64 + t) * 272 + d4 * 2;
            *(uint2*)(base) = hi;
            *(uint2*)(base + 128) = lo;
        }
#pragma unroll
        for (int i = 0; i < 4; i++) {
            int idx = tid + i * 256;
            int jj = idx >> 4, d4 = (idx & 15) * 4;
            float4 v = *(const float4*)(qkv +
                ((size_t)(j0 + jj) * 8 + b) * 3072 + 2048 + h * 64 + d4);
            uint2 hi, lo;
            split4(v, &hi, &lo);
            *(uint2*)(sm + AV + jj * 144 + d4 * 2) = hi;
            *(uint2*)(sm + AV + (64 + jj) * 144 + d4 * 2) = lo;
        }
        if (tid < 128) {
            int l = l0 + tid;
            bbds[tid] = (l < 1024) ? bbd_g[(size_t)h * 1024 + l] : 0.f;
        }
        __syncthreads();

        float sacc[12][4];
#pragma unroll
        for (int j = 0; j < 12; j++)
#pragma unroll
            for (int q = 0; q < 4; q++) sacc[j][q] = 0.f;

#pragma unroll
        for (int ks = 0; ks < 12; ks++) {
            uint32_t a[4];
            ldsm4(a, sb + AQ + (wm * 16 + (lane & 15)) * 272 + aoff[ks] + koff);
#pragma unroll
            for (int nb = 0; nb < 6; nb++) {
                uint32_t bf[4];
                int nr = wn * 96 + nb * 16 + (lane & 15);
                ldsm4(bf, sb + AKS + nr * 272 + boff[ks] + koff);
                mma16816(sacc[nb * 2], a, bf[0], bf[2]);
                mma16816(sacc[nb * 2 + 1], a, bf[1], bf[3]);
            }
        }
        __syncthreads();

        {
            int r = wm * 16 + (lane >> 2);
#pragma unroll
            for (int j = 0; j < 12; j++) {
                int col = wn * 96 + j * 8 + (lane & 3) * 2;
                *(float2*)(sm + AS + (r * 196 + col) * 4) =
                    make_float2(sacc[j][0], sacc[j][1]);
                *(float2*)(sm + AS + ((r + 8) * 196 + col) * 4) =
                    make_float2(sacc[j][2], sacc[j][3]);
            }
        }
        __syncthreads();

        {
            int row = tid >> 2, tq = tid & 3;
            const float* Srow = (const float*)(sm + AS) + row * 196;
            float p[16];
            float rm = -1e30f;
#pragma unroll
            for (int c = 0; c < 16; c++) {
                int jj = tq * 16 + c;
                int t2 = jj - row + 63;
                float val = (Srow[jj] + Srow[64 + t2] + bbds[t2]) * 0.125f;
                bool ok = (j0 + jj) <= (i0 + row + 512);
                p[c] = ok ? val : -1e30f;
                rm = fmaxf(rm, p[c]);
            }
            rm = fmaxf(rm, __shfl_xor_sync(0xffffffffu, rm, 1));
            rm = fmaxf(rm, __shfl_xor_sync(0xffffffffu, rm, 2));
            float mold = msm[row];
            float mnew = fmaxf(mold, rm);
            float rs = 0.f;
#pragma unroll
            for (int c = 0; c < 16; c++) {
                p[c] = __expf(p[c] - mnew);
                rs += p[c];
            }
            rs += __shfl_xor_sync(0xffffffffu, rs, 1);
            rs += __shfl_xor_sync(0xffffffffu, rs, 2);
            if (tq == 0) {
                float cr = __expf(mold - mnew);
                msm[row] = mnew;
                lsm[row] = lsm[row] * cr + rs;
                crs[row] = cr;
            }
            char* pb = sm + AP + row * 272 + tq * 32;
#pragma unroll
            for (int c = 0; c < 16; c += 2) {
                __nv_bfloat162 lo;
                __nv_bfloat162 hi = split_hi2(p[c], p[c + 1], &lo);
                *(uint32_t*)(pb + c * 2) = *(uint32_t*)&hi;
                *(uint32_t*)(pb + 128 + c * 2) = *(uint32_t*)&lo;
            }
        }
        __syncthreads();

        {
            float c0 = crs[wm * 16 + (lane >> 2)];
            float c1 = crs[wm * 16 + 8 + (lane >> 2)];
#pragma unroll
            for (int j = 0; j < 4; j++) {
                oacc[j][0] *= c0; oacc[j][1] *= c0;
                oacc[j][2] *= c1; oacc[j][3] *= c1;
            }
#pragma unroll
            for (int ks = 0; ks < 12; ks++) {
                uint32_t a[4];
                ldsm4(a, sb + AP + (wm * 16 + (lane & 15)) * 272 + aoff[ks] + koff);
#pragma unroll
                for (int nb = 0; nb < 2; nb++) {
                    uint32_t bf[4];
                    int jr = pvjr[ks] + (lane & 7) + 8 * ((lane >> 3) & 1);
                    int dc = wn * 32 + nb * 16 + ((lane >> 4) << 3);
                    ldsm4t(bf, sb + AV + jr * 144 + dc * 2);
                    mma16816(oacc[nb * 2], a, bf[0], bf[1]);
                    mma16816(oacc[nb * 2 + 1], a, bf[2], bf[3]);
                }
            }
        }
    }

    __syncthreads();

    // epilogue: normalize, write awo [hi|lo] (rows 2048 wide)
    {
        int r = wm * 16 + (lane >> 2);
        float inv0 = 1.0f / lsm[r];
        float inv1 = 1.0f / lsm[r + 8];
#pragma unroll
        for (int j = 0; j < 4; j++) {
            int d = wn * 32 + (j >> 1) * 16 + (j & 1) * 8 + (lane & 3) * 2;
            float v0 = oacc[j][0] * inv0, v1 = oacc[j][1] * inv0;
            float v2 = oacc[j][2] * inv1, v3 = oacc[j][3] * inv1;
            __nv_bfloat162 lo0, lo1;
            __nv_bfloat162 h0 = split_hi2(v0, v1, &lo0);
            __nv_bfloat162 h1 = split_hi2(v2, v3, &lo1);
            size_t m0 = (size_t)(i0 + r) * 8 + b;
            size_t m1 = (size_t)(i0 + r + 8) * 8 + b;
            __nv_bfloat16* p0 = outSplit + m0 * 2048 + h * 64 + d;
            __nv_bfloat16* p1 = outSplit + m1 * 2048 + h * 64 + d;
            *(__nv_bfloat162*)(p0) = h0;
            *(__nv_bfloat162*)(p0 + 1024) = lo0;
            *(__nv_bfloat162*)(p1) = h1;
            *(__nv_bfloat162*)(p1 + 1024) = lo1;
        }
    }
}

// ---------------- LayerNorm (+ optional fused [hi|lo] output) ----------------
__global__ __launch_bounds__(256) void ln_kernel(
    const float* __restrict__ x, const float* __restrict__ res,
    const float* __restrict__ g, const float* __restrict__ beta,
    float* __restrict__ out, __nv_bfloat16* __restrict__ outSplit)
{
    __shared__ float red[16];
    const size_t row = blockIdx.x;
    const float* xr = x + row * 1024;
    const float* rr = res + row * 1024;
    float v[4], s = 0.f, ss = 0.f;
#pragma unroll
    for (int i = 0; i < 4; i++) {
        int idx = threadIdx.x + i * 256;
        v[i] = xr[idx] + rr[idx];
        s += v[i];
        ss += v[i] * v[i];
    }
    int lane = threadIdx.x & 31, wid = threadIdx.x >> 5;
#pragma unroll
    for (int off = 16; off >= 1; off >>= 1) {
        s += __shfl_xor_sync(0xffffffffu, s, off);
        ss += __shfl_xor_sync(0xffffffffu, ss, off);
    }
    if (lane == 0) {
        red[wid] = s;
        red[8 + wid] = ss;
    }
    __syncthreads();
    s = 0.f;
    ss = 0.f;
#pragma unroll
    for (int i = 0; i < 8; i++) {
        s += red[i];
        ss += red[8 + i];
    }
    float mean = s * (1.0f / 1024.0f);
    float var = ss * (1.0f / 1024.0f) - mean * mean;
    float rstd = rsqrtf(var + 1e-5f);
#pragma unroll
    for (int i = 0; i < 4; i++) {
        int idx = threadIdx.x + i * 256;
        float y = (v[i] - mean) * rstd * g[idx] + beta[idx];
        out[row * 1024 + idx] = y;
        if (outSplit) {
            __nv_bfloat16 hi = __float2bfloat16(y);
            __nv_bfloat16 lo = __float2bfloat16(y - __bfloat162float(hi));
            __nv_bfloat16* base = outSplit + row * 2048;
            base[idx] = hi;
            base[idx + 1024] = lo;
        }
    }
}

// ---------------- launch (fork/join DAG via side streams) --------------------
static cudaStream_t g_s1 = nullptr, g_s2 = nullptr;
static cudaEvent_t g_evFork, g_evWq, g_evB, g_evC;

extern "C" void kernel_launch(void* const* d_in, const int* in_sizes, int n_in,
                              void* d_out, int out_size)
{
    const float* w    = (const float*)d_in[0];
    const float* r    = (const float*)d_in[1];
    const float* rwb  = (const float*)d_in[2];
    const float* rrb  = (const float*)d_in[3];
    const float* mems = (const float*)d_in[4];
    const float* Wqkv = (const float*)d_in[6];
    const float* Wr   = (const float*)d_in[7];
    const float* Wo   = (const float*)d_in[8];
    const float* ln1g = (const float*)d_in[9];
    const float* ln1b = (const float*)d_in[10];
    const float* W1   = (const float*)d_in[11];
    const float* b1   = (const float*)d_in[12];
    const float* W2   = (const float*)d_in[13];
    const float* b2   = (const float*)d_in[14];
    const float* ln2g = (const float*)d_in[15];
    const float* ln2b = (const float*)d_in[16];
    float* out = (float*)d_out;

    float *qkv, *rk, *bbd, *aout, *out1, *ffo;
    cudaGetSymbolAddress((void**)&qkv, g_qkv);
    cudaGetSymbolAddress((void**)&rk, g_rk);
    cudaGetSymbolAddress((void**)&bbd, g_bbd);
    cudaGetSymbolAddress((void**)&aout, g_attnout);
    cudaGetSymbolAddress((void**)&out1, g_out1);
    cudaGetSymbolAddress((void**)&ffo, g_ffo);

    __nv_bfloat16 *aqkv, *bqkv, *ar, *br, *awo, *bwo, *aff1, *bff1, *aff2, *bff2;
    cudaGetSymbolAddress((void**)&aqkv, g_aqkv);
    cudaGetSymbolAddress((void**)&bqkv, g_bqkv);
    cudaGetSymbolAddress((void**)&ar, g_ar);
    cudaGetSymbolAddress((void**)&br, g_br);
    cudaGetSymbolAddress((void**)&awo, g_awo);
    cudaGetSymbolAddress((void**)&bwo, g_bwo);
    cudaGetSymbolAddress((void**)&aff1, g_aff1);
    cudaGetSymbolAddress((void**)&bff1, g_bff1);
    cudaGetSymbolAddress((void**)&aff2, g_aff2);
    cudaGetSymbolAddress((void**)&bff2, g_bff2);

    cudaFuncSetAttribute(attn_mma3,
                         cudaFuncAttributeMaxDynamicSharedMemorySize,
                         ATT_SMEM);
    cudaFuncSetAttribute(gemm_bf16_mma,
                         cudaFuncAttributeMaxDynamicSharedMemorySize,
                         GEMM_DYN_SMEM);

    if (g_s1 == nullptr) {
        cudaStreamCreateWithFlags(&g_s1, cudaStreamNonBlocking);
        cudaStreamCreateWithFlags(&g_s2, cudaStreamNonBlocking);
        cudaEventCreateWithFlags(&g_evFork, cudaEventDisableTiming);
        cudaEventCreateWithFlags(&g_evWq, cudaEventDisableTiming);
        cudaEventCreateWithFlags(&g_evB, cudaEventDisableTiming);
        cudaEventCreateWithFlags(&g_evC, cudaEventDisableTiming);
    }

    // ---- fork side streams off the main (default) stream ----
    cudaEventRecord(g_evFork, 0);
    cudaStreamWaitEvent(g_s1, g_evFork, 0);
    cudaStreamWaitEvent(g_s2, g_evFork, 0);

    // ---- main stream: A-operand splits for QKV ----
    split3<<<2048, 256>>>(mems, aqkv, 10, 4096LL * 1024);
    split3<<<2048, 256>>>(w, aqkv + 4096LL * 2048, 10, 4096LL * 1024);

    // ---- s1: Wqkv split, then independent rk chain ----
    split3<<<2048, 256, 0, g_s1>>>(Wqkv, bqkv, 10, 3072LL * 1024);
    cudaEventRecord(g_evWq, g_s1);
    split3<<<2048, 256, 0, g_s1>>>(r, ar, 10, 1024LL * 1024);
    split3<<<2048, 256, 0, g_s1>>>(Wr, br, 10, 1024LL * 1024);
    gemm_bf16_mma<<<dim3(8, 8), 256, GEMM_DYN_SMEM, g_s1>>>(
        ar, br, nullptr, rk, nullptr, 1024, 1024, 1024, 0);
    bias_bd_kernel<<<2048, 256, 0, g_s1>>>(rk, rrb, rwb, bbd);
    cudaEventRecord(g_evB, g_s1);

    // ---- s2: weight splits for Wo / W1 / W2 ----
    split3<<<2048, 256, 0, g_s2>>>(Wo, bwo, 10, 1024LL * 1024);
    split3<<<2048, 256, 0, g_s2>>>(W1, bff1, 10, 4096LL * 1024);
    split3<<<2048, 256, 0, g_s2>>>(W2, bff2, 12, 1024LL * 4096);
    cudaEventRecord(g_evC, g_s2);

    // ---- main: QKV GEMM ----
    cudaStreamWaitEvent(0, g_evWq, 0);
    gemm_bf16_mma<<<dim3(24, 64), 256, GEMM_DYN_SMEM>>>(
        aqkv, bqkv, nullptr, qkv, nullptr, 8192, 3072, 1024, 0);

    // ---- join rk chain; attention (bias_ac fused via q+rwb) ----
    cudaStreamWaitEvent(0, g_evB, 0);
    attn_mma3<<<dim3(8, 16, 8), 256, ATT_SMEM>>>(qkv, rk, rwb, bbd, awo);

    // ---- join weight splits; output projection + FFN chain ----
    cudaStreamWaitEvent(0, g_evC, 0);
    gemm_bf16_mma<<<dim3(8, 32), 256, GEMM_DYN_SMEM>>>(
        awo, bwo, nullptr, aout, nullptr, 4096, 1024, 1024, 0);
    ln_kernel<<<4096, 256>>>(aout, w, ln1g, ln1b, out1, aff1);
    gemm_bf16_mma<<<dim3(32, 32), 256, GEMM_DYN_SMEM>>>(
        aff1, bff1, b1, nullptr, aff2, 4096, 4096, 1024, 1);
    gemm_bf16_mma<<<dim3(8, 32), 256, GEMM_DYN_SMEM>>>(
        aff2, bff2, b2, ffo, nullptr, 4096, 1024, 4096, 0);
    ln_kernel<<<4096, 256>>>(ffo, out1, ln2g, ln2b, out, nullptr);
}

// round 17
// speedup vs baseline: 1.0619x; 1.0619x over previous
#include <cuda_runtime.h>
#include <cuda_bf16.h>
#include <cstdint>

// Q=512, M=512, B=8, D=1024, H=16, DH=64, DI=4096, K=1024
#define QLEN 512
#define BSZ 8
#define DMODEL 1024
#define DINNER 4096
#define KLEN 1024

// ---------------- fp32 scratch ----------------------------------------------
__device__ float g_qkv[(size_t)KLEN * BSZ * 3 * DMODEL];     // (k*8+b, 3072)
__device__ float g_rk[(size_t)KLEN * DMODEL];
__device__ float g_bbd[(size_t)16 * KLEN];
__device__ float g_attnout[(size_t)QLEN * BSZ * DMODEL];
__device__ float g_out1[(size_t)QLEN * BSZ * DMODEL];
__device__ float g_ffo[(size_t)QLEN * BSZ * DMODEL];

// ---------------- bf16 split scratch (hi/lo 3K layouts) ---------------------
__device__ __nv_bfloat16 g_aqkv[(size_t)8192 * 3072];
__device__ __nv_bfloat16 g_bqkv[(size_t)3072 * 3072];
__device__ __nv_bfloat16 g_ar[(size_t)1024 * 3072];
__device__ __nv_bfloat16 g_br[(size_t)1024 * 3072];
__device__ __nv_bfloat16 g_awo[(size_t)4096 * 3072];
__device__ __nv_bfloat16 g_bwo[(size_t)1024 * 3072];
__device__ __nv_bfloat16 g_aff1[(size_t)4096 * 3072];
__device__ __nv_bfloat16 g_bff1[(size_t)4096 * 3072];
__device__ __nv_bfloat16 g_aff2[(size_t)4096 * 12288];
__device__ __nv_bfloat16 g_bff2[(size_t)1024 * 12288];

// ---------------- PTX helpers -----------------------------------------------
__device__ __forceinline__ uint32_t smem_u32(const void* p) {
    uint32_t a;
    asm("{ .reg .u64 t; cvta.to.shared.u64 t, %1; cvt.u32.u64 %0, t; }"
        : "=r"(a) : "l"(p));
    return a;
}
#define CP16(dst, src) \
    asm volatile("cp.async.cg.shared.global [%0], [%1], 16;" :: "r"(dst), "l"(src))
#define CP_COMMIT() asm volatile("cp.async.commit_group;" ::: "memory")
#define CP_WAIT2() asm volatile("cp.async.wait_group 2;" ::: "memory")

__device__ __forceinline__ void ldsm4(uint32_t* r, uint32_t addr) {
    asm volatile(
        "ldmatrix.sync.aligned.m8n8.x4.shared.b16 {%0,%1,%2,%3}, [%4];"
        : "=r"(r[0]), "=r"(r[1]), "=r"(r[2]), "=r"(r[3]) : "r"(addr));
}
__device__ __forceinline__ void ldsm4t(uint32_t* r, uint32_t addr) {
    asm volatile(
        "ldmatrix.sync.aligned.m8n8.x4.trans.shared.b16 {%0,%1,%2,%3}, [%4];"
        : "=r"(r[0]), "=r"(r[1]), "=r"(r[2]), "=r"(r[3]) : "r"(addr));
}
__device__ __forceinline__ void mma16816(float* d, const uint32_t* a,
                                         uint32_t b0, uint32_t b1) {
    asm volatile(
        "mma.sync.aligned.m16n8k16.row.col.f32.bf16.bf16.f32 "
        "{%0,%1,%2,%3}, {%4,%5,%6,%7}, {%8,%9}, {%0,%1,%2,%3};"
        : "+f"(d[0]), "+f"(d[1]), "+f"(d[2]), "+f"(d[3])
        : "r"(a[0]), "r"(a[1]), "r"(a[2]), "r"(a[3]), "r"(b0), "r"(b1));
}

__device__ __forceinline__ __nv_bfloat162 split_hi2(float x, float y,
                                                    __nv_bfloat162* lo) {
    __nv_bfloat162 h = __floats2bfloat162_rn(x, y);
    *lo = __floats2bfloat162_rn(x - __bfloat162float(h.x),
                                y - __bfloat162float(h.y));
    return h;
}
__device__ __forceinline__ void split4(float4 v, uint2* hi, uint2* lo) {
    __nv_bfloat162 l01, l23;
    __nv_bfloat162 h01 = split_hi2(v.x, v.y, &l01);
    __nv_bfloat162 h23 = split_hi2(v.z, v.w, &l23);
    hi->x = *(uint32_t*)&h01; hi->y = *(uint32_t*)&h23;
    lo->x = *(uint32_t*)&l01; lo->y = *(uint32_t*)&l23;
}

// ---------------- fp32 -> bf16 hi/lo split conversion ------------------------
// modeA=1: [hi, lo, hi]   modeA=0: [hi, hi, lo]   dst rows have 3K columns.
__global__ __launch_bounds__(256) void split3(const float* __restrict__ src,
                                              __nv_bfloat16* __restrict__ dst,
                                              int lk, long long n, int modeA)
{
    long long K = 1LL << lk;
    long long i0 = ((long long)blockIdx.x * 256 + threadIdx.x) * 4;
    long long step = (long long)gridDim.x * 256 * 4;
    for (long long e = i0; e < n; e += step) {
        long long r = e >> lk;
        long long k = e & (K - 1);
        float4 v = *(const float4*)(src + e);
        __nv_bfloat162 l01, l23;
        __nv_bfloat162 h01 = split_hi2(v.x, v.y, &l01);
        __nv_bfloat162 h23 = split_hi2(v.z, v.w, &l23);
        __nv_bfloat16* base = dst + r * (K * 3) + k;
        *(__nv_bfloat162*)(base) = h01;
        *(__nv_bfloat162*)(base + 2) = h23;
        *(__nv_bfloat162*)(base + K) = modeA ? l01 : h01;
        *(__nv_bfloat162*)(base + K + 2) = modeA ? l23 : h23;
        *(__nv_bfloat162*)(base + 2 * K) = modeA ? h01 : l01;
        *(__nv_bfloat162*)(base + 2 * K + 2) = modeA ? h23 : l23;
    }
}

// ---------------- bf16 tensor-core GEMM via mma.sync (EXACT R7) --------------
#define STAGE_BYTES 32768
#define GEMM_DYN_SMEM (3 * STAGE_BYTES)
#define SWZ(x) ((x) ^ (((x) >> 3) & 0x70))

__global__ __launch_bounds__(256, 2) void gemm_bf16_mma(
    const __nv_bfloat16* __restrict__ A, const __nv_bfloat16* __restrict__ B,
    const float* __restrict__ bias, float* __restrict__ C,
    __nv_bfloat16* __restrict__ Csplit,
    int M, int N, int K3, int relu)
{
    extern __shared__ char dynsm[];
    const int tid = threadIdx.x;
    const int wid = tid >> 5, lane = tid & 31;
    const int wm = wid & 3, wn = wid >> 2;
    const int bm = blockIdx.y * 128, bn = blockIdx.x * 128;
    const int nchunks = K3 >> 6;
    const uint32_t smbase = smem_u32(dynsm);

    const size_t rowBytes = (size_t)K3 * 2;

    uint32_t dstOff[4];
    const char* srcA[4];
    const char* srcB[4];
    {
        int r0 = tid >> 3;
        int c16 = (tid & 7) << 4;
#pragma unroll
        for (int i = 0; i < 4; i++) {
            int row = r0 + i * 32;
            dstOff[i] = SWZ((uint32_t)(row * 128 + c16));
            srcA[i] = (const char*)A + (size_t)(bm + row) * rowBytes + c16;
            srcB[i] = (const char*)B + (size_t)(bn + row) * rowBytes + c16;
        }
    }

    float acc[2][8][4];
#pragma unroll
    for (int t = 0; t < 2; t++)
#pragma unroll
        for (int j = 0; j < 8; j++)
#pragma unroll
            for (int q = 0; q < 4; q++) acc[t][j][q] = 0.f;

    auto issue_copies = [&](int chunk) {
        uint32_t sb = smbase + (chunk % 3) * STAGE_BYTES;
#pragma unroll
        for (int i = 0; i < 4; i++) {
            CP16(sb + dstOff[i], srcA[i]);
            srcA[i] += 128;
        }
#pragma unroll
        for (int i = 0; i < 4; i++) {
            CP16(sb + 16384 + dstOff[i], srcB[i]);
            srcB[i] += 128;
        }
    };

    issue_copies(0); CP_COMMIT();
    issue_copies(1); CP_COMMIT();

    uint32_t preA[2], preB[4];
#pragma unroll
    for (int t = 0; t < 2; t++) {
        int row = wm * 32 + t * 16 + (lane & 15);
        preA[t] = (uint32_t)(row * 128 + ((row & 7) << 4));
    }
#pragma unroll
    for (int p = 0; p < 4; p++) {
        int row = wn * 64 + p * 16 + (lane & 15);
        preB[p] = (uint32_t)(row * 128 + ((row & 7) << 4));
    }
    const uint32_t kbase = (uint32_t)((lane >> 4) << 4);

    for (int c = 0; c < nchunks; c++) {
        if (c + 2 < nchunks) issue_copies(c + 2);
        CP_COMMIT();
        CP_WAIT2();
        __syncthreads();

        const uint32_t sA = smbase + (c % 3) * STAGE_BYTES;
        const uint32_t sB = sA + 16384;

#pragma unroll
        for (int kk = 0; kk < 4; kk++) {
            const uint32_t kb = (uint32_t)(kk * 32) + kbase;
            uint32_t a[2][4], b[4][4];
#pragma unroll
            for (int t = 0; t < 2; t++) ldsm4(a[t], sA + (preA[t] ^ kb));
#pragma unroll
            for (int p = 0; p < 4; p++) ldsm4(b[p], sB + (preB[p] ^ kb));
#pragma unroll
            for (int t = 0; t < 2; t++)
#pragma unroll
                for (int j = 0; j < 8; j++)
                    mma16816(acc[t][j], a[t], b[j >> 1][j & 1],
                             b[j >> 1][2 + (j & 1)]);
        }
        __syncthreads();
    }

#pragma unroll
    for (int t = 0; t < 2; t++) {
        int row0 = bm + wm * 32 + t * 16 + (lane >> 2);
#pragma unroll
        for (int j = 0; j < 8; j++) {
            int col = bn + wn * 64 + j * 8 + (lane & 3) * 2;
            float bx = 0.f, by = 0.f;
            if (bias) { bx = bias[col]; by = bias[col + 1]; }
            float2 v0 = make_float2(acc[t][j][0] + bx, acc[t][j][1] + by);
            float2 v1 = make_float2(acc[t][j][2] + bx, acc[t][j][3] + by);
            if (relu) {
                v0.x = fmaxf(v0.x, 0.f); v0.y = fmaxf(v0.y, 0.f);
                v1.x = fmaxf(v1.x, 0.f); v1.y = fmaxf(v1.y, 0.f);
            }
            if (C) {
                *(float2*)(C + (size_t)row0 * N + col) = v0;
                *(float2*)(C + (size_t)(row0 + 8) * N + col) = v1;
            }
            if (Csplit) {
                __nv_bfloat162 lo0, lo1;
                __nv_bfloat162 h0 = split_hi2(v0.x, v0.y, &lo0);
                __nv_bfloat162 h1 = split_hi2(v1.x, v1.y, &lo1);
                __nv_bfloat16* p0 = Csplit + (size_t)row0 * (3 * N) + col;
                __nv_bfloat16* p1 = Csplit + (size_t)(row0 + 8) * (3 * N) + col;
                *(__nv_bfloat162*)(p0) = h0;
                *(__nv_bfloat162*)(p0 + N) = lo0;
                *(__nv_bfloat162*)(p0 + 2 * N) = h0;
                *(__nv_bfloat162*)(p1) = h1;
                *(__nv_bfloat162*)(p1 + N) = lo1;
                *(__nv_bfloat162*)(p1 + 2 * N) = h1;
            }
        }
    }
}

// ---------------- bias dot: bbd[h,l] = (rrb-rwb)[h,:] . rk[l,h,:] ------------
__global__ void bias_bd_kernel(const float* __restrict__ rk,
                               const float* __restrict__ rrb,
                               const float* __restrict__ rwb,
                               float* __restrict__ out)
{
    int warp = (blockIdx.x * blockDim.x + threadIdx.x) >> 5;
    int lane = threadIdx.x & 31;
    int l = warp & 1023;
    int h = warp >> 10;
    const float* kp = rk + (size_t)l * 1024 + h * 64;
    float w0 = rrb[h * 64 + lane] - rwb[h * 64 + lane];
    float w1 = rrb[h * 64 + lane + 32] - rwb[h * 64 + lane + 32];
    float v = kp[lane] * w0 + kp[lane + 32] * w1;
#pragma unroll
    for (int off = 16; off >= 1; off >>= 1)
        v += __shfl_xor_sync(0xffffffffu, v, off);
    if (lane == 0) out[warp] = v;
}

// ---------------- MMA rel-shift flash attention (q+rwb fused, R14 core) ------
#define AQ   0
#define AKS  17408
#define AS   17408
#define AV   69632
#define AP   88064
#define ABBD 105728
#define AMS  106240
#define ALS  106496
#define ACR  106752
#define ATT_SMEM 107008

__global__ __launch_bounds__(256, 2) void attn_mma3(
    const float* __restrict__ qkv, const float* __restrict__ rkG,
    const float* __restrict__ rwb, const float* __restrict__ bbd_g,
    __nv_bfloat16* __restrict__ outSplit)
{
    extern __shared__ char sm[];
    const uint32_t sb = smem_u32(sm);
    const int tid = threadIdx.x, lane = tid & 31, wid = tid >> 5;
    const int wm = wid & 3, wn = wid >> 2;
    const int i0 = blockIdx.x * 64, h = blockIdx.y, b = blockIdx.z;

    float* msm = (float*)(sm + AMS);
    float* lsm = (float*)(sm + ALS);
    float* crs = (float*)(sm + ACR);
    float* bbds = (float*)(sm + ABBD);

    if (tid < 64) { msm[tid] = -1e30f; lsm[tid] = 0.f; }

    // q tile: fp32 load + rwb bias, split -> [hi 128B | lo 128B], stride 272
#pragma unroll
    for (int i = 0; i < 4; i++) {
        int idx = tid + i * 256;
        int row = idx >> 4, d4 = (idx & 15) * 4;
        float4 v = *(const float4*)(qkv +
            ((size_t)(512 + i0 + row) * 8 + b) * 3072 + h * 64 + d4);
        float4 wv = *(const float4*)(rwb + h * 64 + d4);
        v.x += wv.x; v.y += wv.y; v.z += wv.z; v.w += wv.w;
        uint2 hi, lo;
        split4(v, &hi, &lo);
        char* base = sm + AQ + row * 272 + d4 * 2;
        *(uint2*)(base) = hi;
        *(uint2*)(base + 128) = lo;
    }

    float oacc[4][4];
#pragma unroll
    for (int j = 0; j < 4; j++)
#pragma unroll
        for (int q = 0; q < 4; q++) oacc[j][q] = 0.f;

    const int aoff[12] = {0,32,64,96, 128,160,192,224, 0,32,64,96};
    const int boff[12] = {0,32,64,96, 0,32,64,96, 128,160,192,224};
    const int pvjr[12] = {0,16,32,48, 0,16,32,48, 64,80,96,112};

    const int n_jt = min(16, (int)blockIdx.x + 9);
    const uint32_t koff = (uint32_t)((lane >> 4) << 4);

    for (int jt = 0; jt < n_jt; jt++) {
        const int j0 = jt * 64;
        const int l0 = j0 + 448 - i0;

        __syncthreads();

#pragma unroll
        for (int i = 0; i < 4; i++) {
            int idx = tid + i * 256;
            int jj = idx >> 4, d4 = (idx & 15) * 4;
            float4 v = *(const float4*)(qkv +
                ((size_t)(j0 + jj) * 8 + b) * 3072 + 1024 + h * 64 + d4);
            uint2 hi, lo;
            split4(v, &hi, &lo);
            char* base = sm + AKS + jj * 272 + d4 * 2;
            *(uint2*)(base) = hi;
            *(uint2*)(base + 128) = lo;
        }
#pragma unroll
        for (int i = 0; i < 8; i++) {
            int idx = tid + i * 256;
            int t = idx >> 4, d4 = (idx & 15) * 4;
            int l = l0 + t;
            float4 v = make_float4(0.f, 0.f, 0.f, 0.f);
            if (l < 1024)
                v = *(const float4*)(rkG + (size_t)l * 1024 + h * 64 + d4);
            uint2 hi, lo;
            split4(v, &hi, &lo);
            char* base = sm + AKS + (64 + t) * 272 + d4 * 2;
            *(uint2*)(base) = hi;
            *(uint2*)(base + 128) = lo;
        }
#pragma unroll
        for (int i = 0; i < 4; i++) {
            int idx = tid + i * 256;
            int jj = idx >> 4, d4 = (idx & 15) * 4;
            float4 v = *(const float4*)(qkv +
                ((size_t)(j0 + jj) * 8 + b) * 3072 + 2048 + h * 64 + d4);
            uint2 hi, lo;
            split4(v, &hi, &lo);
            *(uint2*)(sm + AV + jj * 144 + d4 * 2) = hi;
            *(uint2*)(sm + AV + (64 + jj) * 144 + d4 * 2) = lo;
        }
        if (tid < 128) {
            int l = l0 + tid;
            bbds[tid] = (l < 1024) ? bbd_g[(size_t)h * 1024 + l] : 0.f;
        }
        __syncthreads();

        float sacc[12][4];
#pragma unroll
        for (int j = 0; j < 12; j++)
#pragma unroll
            for (int q = 0; q < 4; q++) sacc[j][q] = 0.f;

#pragma unroll
        for (int ks = 0; ks < 12; ks++) {
            uint32_t a[4];
            ldsm4(a, sb + AQ + (wm * 16 + (lane & 15)) * 272 + aoff[ks] + koff);
#pragma unroll
            for (int nb = 0; nb < 6; nb++) {
                uint32_t bf[4];
                int nr = wn * 96 + nb * 16 + (lane & 15);
                ldsm4(bf, sb + AKS + nr * 272 + boff[ks] + koff);
                mma16816(sacc[nb * 2], a, bf[0], bf[2]);
                mma16816(sacc[nb * 2 + 1], a, bf[1], bf[3]);
            }
        }
        __syncthreads();

        {
            int r = wm * 16 + (lane >> 2);
#pragma unroll
            for (int j = 0; j < 12; j++) {
                int col = wn * 96 + j * 8 + (lane & 3) * 2;
                *(float2*)(sm + AS + (r * 196 + col) * 4) =
                    make_float2(sacc[j][0], sacc[j][1]);
                *(float2*)(sm + AS + ((r + 8) * 196 + col) * 4) =
                    make_float2(sacc[j][2], sacc[j][3]);
            }
        }
        __syncthreads();

        {
            int row = tid >> 2, tq = tid & 3;
            const float* Srow = (const float*)(sm + AS) + row * 196;
            float p[16];
            float rm = -1e30f;
#pragma unroll
            for (int c = 0; c < 16; c++) {
                int jj = tq * 16 + c;
                int t2 = jj - row + 63;
                float val = (Srow[jj] + Srow[64 + t2] + bbds[t2]) * 0.125f;
                bool ok = (j0 + jj) <= (i0 + row + 512);
                p[c] = ok ? val : -1e30f;
                rm = fmaxf(rm, p[c]);
            }
            rm = fmaxf(rm, __shfl_xor_sync(0xffffffffu, rm, 1));
            rm = fmaxf(rm, __shfl_xor_sync(0xffffffffu, rm, 2));
            float mold = msm[row];
            float mnew = fmaxf(mold, rm);
            float rs = 0.f;
#pragma unroll
            for (int c = 0; c < 16; c++) {
                p[c] = __expf(p[c] - mnew);
                rs += p[c];
            }
            rs += __shfl_xor_sync(0xffffffffu, rs, 1);
            rs += __shfl_xor_sync(0xffffffffu, rs, 2);
            if (tq == 0) {
                float cr = __expf(mold - mnew);
                msm[row] = mnew;
                lsm[row] = lsm[row] * cr + rs;
                crs[row] = cr;
            }
            char* pb = sm + AP + row * 272 + tq * 32;
#pragma unroll
            for (int c = 0; c < 16; c += 2) {
                __nv_bfloat162 lo;
                __nv_bfloat162 hi = split_hi2(p[c], p[c + 1], &lo);
                *(uint32_t*)(pb + c * 2) = *(uint32_t*)&hi;
                *(uint32_t*)(pb + 128 + c * 2) = *(uint32_t*)&lo;
            }
        }
        __syncthreads();

        {
            float c0 = crs[wm * 16 + (lane >> 2)];
            float c1 = crs[wm * 16 + 8 + (lane >> 2)];
#pragma unroll
            for (int j = 0; j < 4; j++) {
                oacc[j][0] *= c0; oacc[j][1] *= c0;
                oacc[j][2] *= c1; oacc[j][3] *= c1;
            }
#pragma unroll
            for (int ks = 0; ks < 12; ks++) {
                uint32_t a[4];
                ldsm4(a, sb + AP + (wm * 16 + (lane & 15)) * 272 + aoff[ks] + koff);
#pragma unroll
                for (int nb = 0; nb < 2; nb++) {
                    uint32_t bf[4];
                    int jr = pvjr[ks] + (lane & 7) + 8 * ((lane >> 3) & 1);
                    int dc = wn * 32 + nb * 16 + ((lane >> 4) << 3);
                    ldsm4t(bf, sb + AV + jr * 144 + dc * 2);
                    mma16816(oacc[nb * 2], a, bf[0], bf[1]);
                    mma16816(oacc[nb * 2 + 1], a, bf[2], bf[3]);
                }
            }
        }
    }

    __syncthreads();

    // epilogue: normalize, write awo in 3K split layout ([hi,lo,hi], 3072 wide)
    {
        int r = wm * 16 + (lane >> 2);
        float inv0 = 1.0f / lsm[r];
        float inv1 = 1.0f / lsm[r + 8];
#pragma unroll
        for (int j = 0; j < 4; j++) {
            int d = wn * 32 + (j >> 1) * 16 + (j & 1) * 8 + (lane & 3) * 2;
            float v0 = oacc[j][0] * inv0, v1 = oacc[j][1] * inv0;
            float v2 = oacc[j][2] * inv1, v3 = oacc[j][3] * inv1;
            __nv_bfloat162 lo0, lo1;
            __nv_bfloat162 h0 = split_hi2(v0, v1, &lo0);
            __nv_bfloat162 h1 = split_hi2(v2, v3, &lo1);
            size_t m0 = (size_t)(i0 + r) * 8 + b;
            size_t m1 = (size_t)(i0 + r + 8) * 8 + b;
            __nv_bfloat16* p0 = outSplit + m0 * 3072 + h * 64 + d;
            __nv_bfloat16* p1 = outSplit + m1 * 3072 + h * 64 + d;
            *(__nv_bfloat162*)(p0) = h0;
            *(__nv_bfloat162*)(p0 + 1024) = lo0;
            *(__nv_bfloat162*)(p0 + 2048) = h0;
            *(__nv_bfloat162*)(p1) = h1;
            *(__nv_bfloat162*)(p1 + 1024) = lo1;
            *(__nv_bfloat162*)(p1 + 2048) = h1;
        }
    }
}

// ---------------- LayerNorm (+ optional fused A-split output) ----------------
__global__ __launch_bounds__(256) void ln_kernel(
    const float* __restrict__ x, const float* __restrict__ res,
    const float* __restrict__ g, const float* __restrict__ beta,
    float* __restrict__ out, __nv_bfloat16* __restrict__ outSplit)
{
    __shared__ float red[16];
    const size_t row = blockIdx.x;
    const float* xr = x + row * 1024;
    const float* rr = res + row * 1024;
    float v[4], s = 0.f, ss = 0.f;
#pragma unroll
    for (int i = 0; i < 4; i++) {
        int idx = threadIdx.x + i * 256;
        v[i] = xr[idx] + rr[idx];
        s += v[i];
        ss += v[i] * v[i];
    }
    int lane = threadIdx.x & 31, wid = threadIdx.x >> 5;
#pragma unroll
    for (int off = 16; off >= 1; off >>= 1) {
        s += __shfl_xor_sync(0xffffffffu, s, off);
        ss += __shfl_xor_sync(0xffffffffu, ss, off);
    }
    if (lane == 0) {
        red[wid] = s;
        red[8 + wid] = ss;
    }
    __syncthreads();
    s = 0.f;
    ss = 0.f;
#pragma unroll
    for (int i = 0; i < 8; i++) {
        s += red[i];
        ss += red[8 + i];
    }
    float mean = s * (1.0f / 1024.0f);
    float var = ss * (1.0f / 1024.0f) - mean * mean;
    float rstd = rsqrtf(var + 1e-5f);
#pragma unroll
    for (int i = 0; i < 4; i++) {
        int idx = threadIdx.x + i * 256;
        float y = (v[i] - mean) * rstd * g[idx] + beta[idx];
        out[row * 1024 + idx] = y;
        if (outSplit) {
            __nv_bfloat16 hi = __float2bfloat16(y);
            __nv_bfloat16 lo = __float2bfloat16(y - __bfloat162float(hi));
            __nv_bfloat16* base = outSplit + row * 3072;
            base[idx] = hi;
            base[idx + 1024] = lo;
            base[idx + 2048] = hi;
        }
    }
}

// ---------------- launch (fork/join DAG via side streams) --------------------
static cudaStream_t g_s1 = nullptr, g_s2 = nullptr;
static cudaEvent_t g_evFork, g_evWq, g_evB, g_evC;

extern "C" void kernel_launch(void* const* d_in, const int* in_sizes, int n_in,
                              void* d_out, int out_size)
{
    const float* w    = (const float*)d_in[0];
    const float* r    = (const float*)d_in[1];
    const float* rwb  = (const float*)d_in[2];
    const float* rrb  = (const float*)d_in[3];
    const float* mems = (const float*)d_in[4];
    const float* Wqkv = (const float*)d_in[6];
    const float* Wr   = (const float*)d_in[7];
    const float* Wo   = (const float*)d_in[8];
    const float* ln1g = (const float*)d_in[9];
    const float* ln1b = (const float*)d_in[10];
    const float* W1   = (const float*)d_in[11];
    const float* b1   = (const float*)d_in[12];
    const float* W2   = (const float*)d_in[13];
    const float* b2   = (const float*)d_in[14];
    const float* ln2g = (const float*)d_in[15];
    const float* ln2b = (const float*)d_in[16];
    float* out = (float*)d_out;

    float *qkv, *rk, *bbd, *aout, *out1, *ffo;
    cudaGetSymbolAddress((void**)&qkv, g_qkv);
    cudaGetSymbolAddress((void**)&rk, g_rk);
    cudaGetSymbolAddress((void**)&bbd, g_bbd);
    cudaGetSymbolAddress((void**)&aout, g_attnout);
    cudaGetSymbolAddress((void**)&out1, g_out1);
    cudaGetSymbolAddress((void**)&ffo, g_ffo);

    __nv_bfloat16 *aqkv, *bqkv, *ar, *br, *awo, *bwo, *aff1, *bff1, *aff2, *bff2;
    cudaGetSymbolAddress((void**)&aqkv, g_aqkv);
    cudaGetSymbolAddress((void**)&bqkv, g_bqkv);
    cudaGetSymbolAddress((void**)&ar, g_ar);
    cudaGetSymbolAddress((void**)&br, g_br);
    cudaGetSymbolAddress((void**)&awo, g_awo);
    cudaGetSymbolAddress((void**)&bwo, g_bwo);
    cudaGetSymbolAddress((void**)&aff1, g_aff1);
    cudaGetSymbolAddress((void**)&bff1, g_bff1);
    cudaGetSymbolAddress((void**)&aff2, g_aff2);
    cudaGetSymbolAddress((void**)&bff2, g_bff2);

    cudaFuncSetAttribute(attn_mma3,
                         cudaFuncAttributeMaxDynamicSharedMemorySize,
                         ATT_SMEM);
    cudaFuncSetAttribute(gemm_bf16_mma,
                         cudaFuncAttributeMaxDynamicSharedMemorySize,
                         GEMM_DYN_SMEM);

    if (g_s1 == nullptr) {
        cudaStreamCreateWithFlags(&g_s1, cudaStreamNonBlocking);
        cudaStreamCreateWithFlags(&g_s2, cudaStreamNonBlocking);
        cudaEventCreateWithFlags(&g_evFork, cudaEventDisableTiming);
        cudaEventCreateWithFlags(&g_evWq, cudaEventDisableTiming);
        cudaEventCreateWithFlags(&g_evB, cudaEventDisableTiming);
        cudaEventCreateWithFlags(&g_evC, cudaEventDisableTiming);
    }

    // ---- fork side streams off the main (default) stream ----
    cudaEventRecord(g_evFork, 0);
    cudaStreamWaitEvent(g_s1, g_evFork, 0);
    cudaStreamWaitEvent(g_s2, g_evFork, 0);

    // ---- main stream: A-operand splits for QKV ----
    split3<<<2048, 256>>>(mems, aqkv, 10, 4096LL * 1024, 1);
    split3<<<2048, 256>>>(w, aqkv + 4096LL * 3072, 10, 4096LL * 1024, 1);

    // ---- s1: Wqkv split, then independent rk chain ----
    split3<<<2048, 256, 0, g_s1>>>(Wqkv, bqkv, 10, 3072LL * 1024, 0);
    cudaEventRecord(g_evWq, g_s1);
    split3<<<2048, 256, 0, g_s1>>>(r, ar, 10, 1024LL * 1024, 1);
    split3<<<2048, 256, 0, g_s1>>>(Wr, br, 10, 1024LL * 1024, 0);
    gemm_bf16_mma<<<dim3(8, 8), 256, GEMM_DYN_SMEM, g_s1>>>(
        ar, br, nullptr, rk, nullptr, 1024, 1024, 3072, 0);
    bias_bd_kernel<<<2048, 256, 0, g_s1>>>(rk, rrb, rwb, bbd);
    cudaEventRecord(g_evB, g_s1);

    // ---- s2: weight splits for Wo / W1 / W2 ----
    split3<<<2048, 256, 0, g_s2>>>(Wo, bwo, 10, 1024LL * 1024, 0);
    split3<<<2048, 256, 0, g_s2>>>(W1, bff1, 10, 4096LL * 1024, 0);
    split3<<<2048, 256, 0, g_s2>>>(W2, bff2, 12, 1024LL * 4096, 0);
    cudaEventRecord(g_evC, g_s2);

    // ---- main: QKV GEMM ----
    cudaStreamWaitEvent(0, g_evWq, 0);
    gemm_bf16_mma<<<dim3(24, 64), 256, GEMM_DYN_SMEM>>>(
        aqkv, bqkv, nullptr, qkv, nullptr, 8192, 3072, 3072, 0);

    // ---- join rk chain; attention (bias_ac fused via q+rwb) ----
    cudaStreamWaitEvent(0, g_evB, 0);
    attn_mma3<<<dim3(8, 16, 8), 256, ATT_SMEM>>>(qkv, rk, rwb, bbd, awo);

    // ---- join weight splits; output projection + FFN chain ----
    cudaStreamWaitEvent(0, g_evC, 0);
    gemm_bf16_mma<<<dim3(8, 32), 256, GEMM_DYN_SMEM>>>(
        awo, bwo, nullptr, aout, nullptr, 4096, 1024, 3072, 0);
    ln_kernel<<<4096, 256>>>(aout, w, ln1g, ln1b, out1, aff1);
    gemm_bf16_mma<<<dim3(32, 32), 256, GEMM_DYN_SMEM>>>(
        aff1, bff1, b1, nullptr, aff2, 4096, 4096, 3072, 1);
    gemm_bf16_mma<<<dim3(8, 32), 256, GEMM_DYN_SMEM>>>(
        aff2, bff2, b2, ffo, nullptr, 4096, 1024, 12288, 0);
    ln_kernel<<<4096, 256>>>(ffo, out1, ln2g, ln2b, out, nullptr);
}